// round 2
// baseline (speedup 1.0000x reference)
#include <cuda_runtime.h>
#include <cuda_bf16.h>

#define NN 100000
#define EE 1000000
#define HID 64
#define NCHUNK 1024
#define NBLK 98            // ceil(NN / NCHUNK)
#define BN_EPS 1e-5f

// ---------------- scratch (__device__ globals: allowed, no runtime alloc) ----
__device__ __align__(16) int   g_deg[NN];
__device__ __align__(16) float g_dinv[NN];
__device__ __align__(16) int   g_rowptr[NN + 1];
__device__ __align__(16) int   g_cursor[NN];
__device__ __align__(16) int   g_src[EE + NN];
__device__ __align__(16) float g_h[NN * HID];
__device__ __align__(16) float g_x1[NN * HID];
__device__ __align__(16) float g_x2[NN * HID];
__device__ __align__(16) int   g_bsum[128];

// ---------------- preprocessing ---------------------------------------------

__global__ void init_deg_kernel() {
    int i = blockIdx.x * blockDim.x + threadIdx.x;
    if (i < NN) g_deg[i] = 1;          // self loop
}

// edge_index is int32 (JAX downcasts int64 without x64 mode): ei[0..EE)=src, ei[EE..2EE)=dst
__global__ void count_kernel(const int* __restrict__ col) {
    int i = blockIdx.x * blockDim.x + threadIdx.x;
    if (i < EE) {
        unsigned c = (unsigned)col[i];
        if (c < NN) atomicAdd(&g_deg[c], 1);
    }
}

// per-1024-chunk degree sums + dinv
__global__ void partials_kernel() {
    int tid = threadIdx.x, b = blockIdx.x;
    int base = b * NCHUNK + tid * 4;
    int s = 0;
#pragma unroll
    for (int j = 0; j < 4; j++) {
        int idx = base + j;
        if (idx < NN) {
            int d = g_deg[idx];
            s += d;
            g_dinv[idx] = rsqrtf((float)d);
        }
    }
    for (int d = 16; d; d >>= 1) s += __shfl_down_sync(0xffffffffu, s, d);
    __shared__ int wsum[8];
    int lane = tid & 31, wid = tid >> 5;
    if (lane == 0) wsum[wid] = s;
    __syncthreads();
    if (tid == 0) {
        int t = 0;
#pragma unroll
        for (int i = 0; i < 8; i++) t += wsum[i];
        g_bsum[b] = t;
    }
}

__global__ void scan_top_kernel() {
    __shared__ int sh[128];
    int t = threadIdx.x;
    sh[t] = (t < NBLK) ? g_bsum[t] : 0;
    __syncthreads();
    if (t == 0) {
        int run = 0;
        for (int i = 0; i < NBLK; i++) { int v = sh[i]; sh[i] = run; run += v; }
        g_rowptr[NN] = run;
    }
    __syncthreads();
    if (t < NBLK) g_bsum[t] = sh[t];   // exclusive chunk offsets
}

__global__ void scan_chunks_kernel() {
    int b = blockIdx.x, tid = threadIdx.x;
    int lane = tid & 31, wid = tid >> 5;
    int base = b * NCHUNK + tid * 4;
    int v[4]; int s = 0;
#pragma unroll
    for (int j = 0; j < 4; j++) {
        int idx = base + j;
        v[j] = (idx < NN) ? g_deg[idx] : 0;
        s += v[j];
    }
    int x = s;
#pragma unroll
    for (int d = 1; d < 32; d <<= 1) {
        int y = __shfl_up_sync(0xffffffffu, x, d);
        if (lane >= d) x += y;
    }
    __shared__ int wsum[8], woff[8];
    if (lane == 31) wsum[wid] = x;
    __syncthreads();
    if (tid == 0) {
        int run = 0;
#pragma unroll
        for (int i = 0; i < 8; i++) { int t = wsum[i]; woff[i] = run; run += t; }
    }
    __syncthreads();
    int pos = g_bsum[b] + woff[wid] + (x - s);
#pragma unroll
    for (int j = 0; j < 4; j++) {
        int idx = base + j;
        if (idx < NN) {
            g_rowptr[idx] = pos;
            g_cursor[idx] = pos;
            pos += v[j];
        }
    }
}

__global__ void bin_kernel(const int* __restrict__ ei) {
    int i = blockIdx.x * blockDim.x + threadIdx.x;
    if (i >= EE + NN) return;
    unsigned s, c;
    if (i < EE) { s = (unsigned)ei[i]; c = (unsigned)ei[EE + i]; }
    else        { s = c = (unsigned)(i - EE); }
    if (s >= NN || c >= NN) return;
    int p = atomicAdd(&g_cursor[c], 1);
    if ((unsigned)p < (unsigned)(EE + NN)) g_src[p] = (int)s;
}

// ---------------- GEMM: h[n,:] = dinv[n] * (X[n,:] @ W) ----------------------
// 64 nodes / block, 256 threads, 4x4 register tile per thread.
template <int K>
__global__ void gemm_kernel(const float* __restrict__ Xext,
                            const float* __restrict__ W, int layer) {
    __shared__ __align__(16) float xs[64 * K];
    __shared__ __align__(16) float ws[K * HID];
    const float* X = Xext ? Xext : (layer == 1 ? (const float*)g_x1 : (const float*)g_x2);

    const int tid  = threadIdx.x;
    const int base = blockIdx.x * 64;

    for (int i = tid; i < K * HID; i += 256) ws[i] = W[i];
    for (int i = tid; i < 64 * K; i += 256) {
        int n = base + i / K;
        xs[i] = (n < NN) ? X[(size_t)base * K + i] : 0.0f;
    }
    __syncthreads();

    const int cgrp = tid & 15;   // 16 col groups x 4 cols
    const int ngrp = tid >> 4;   // 16 node groups x 4 nodes
    float acc[4][4];
#pragma unroll
    for (int j = 0; j < 4; j++)
#pragma unroll
        for (int q = 0; q < 4; q++) acc[j][q] = 0.0f;

#pragma unroll 4
    for (int k = 0; k < K; k++) {
        float4 w4 = *(const float4*)&ws[k * HID + cgrp * 4];
#pragma unroll
        for (int j = 0; j < 4; j++) {
            float xv = xs[(ngrp * 4 + j) * K + k];
            acc[j][0] += xv * w4.x;
            acc[j][1] += xv * w4.y;
            acc[j][2] += xv * w4.z;
            acc[j][3] += xv * w4.w;
        }
    }

#pragma unroll
    for (int j = 0; j < 4; j++) {
        int n = base + ngrp * 4 + j;
        if (n < NN) {
            float di = g_dinv[n];
            float4 o = make_float4(di * acc[j][0], di * acc[j][1],
                                   di * acc[j][2], di * acc[j][3]);
            *(float4*)&g_h[n * HID + cgrp * 4] = o;
        }
    }
}

// ---------------- SpMM (gather, CSR) + fused BN/ReLU/residual epilogue -------
// one warp per node, 2 cols per lane (float2), unroll-2 ILP
__global__ void spmm_epi_kernel(int layer,
                                const float* __restrict__ bias,
                                const float* __restrict__ gamma,
                                const float* __restrict__ beta,
                                const float* __restrict__ mean,
                                const float* __restrict__ var,
                                float* __restrict__ out_final) {
    int gw = (blockIdx.x * blockDim.x + threadIdx.x) >> 5;
    if (gw >= NN) return;
    int lane = threadIdx.x & 31;
    int c = lane * 2;

    const float* __restrict__ H = g_h;
    const float* resid = (layer == 0) ? nullptr
                        : (layer == 1 ? (const float*)g_x1 : (const float*)g_x2);
    float* out = (layer == 0) ? g_x1 : (layer == 1 ? g_x2 : out_final);

    int beg = g_rowptr[gw];
    int end = g_rowptr[gw + 1];

    float2 a0 = make_float2(0.f, 0.f), a1 = make_float2(0.f, 0.f);
    int e = beg;
    for (; e + 1 < end; e += 2) {
        int s0 = g_src[e], s1 = g_src[e + 1];
        float2 v0 = *(const float2*)(H + s0 * HID + c);
        float2 v1 = *(const float2*)(H + s1 * HID + c);
        a0.x += v0.x; a0.y += v0.y;
        a1.x += v1.x; a1.y += v1.y;
    }
    if (e < end) {
        int s = g_src[e];
        float2 v = *(const float2*)(H + s * HID + c);
        a0.x += v.x; a0.y += v.y;
    }

    float di = g_dinv[gw];
    float scx = gamma[c]     * rsqrtf(var[c]     + BN_EPS);
    float scy = gamma[c + 1] * rsqrtf(var[c + 1] + BN_EPS);
    float vx = ((a0.x + a1.x) * di + bias[c]     - mean[c])     * scx + beta[c];
    float vy = ((a0.y + a1.y) * di + bias[c + 1] - mean[c + 1]) * scy + beta[c + 1];
    vx = fmaxf(vx, 0.0f);
    vy = fmaxf(vy, 0.0f);
    if (resid) {
        float2 r = *(const float2*)(resid + gw * HID + c);
        vx += r.x; vy += r.y;
    }
    *(float2*)(out + gw * HID + c) = make_float2(vx, vy);
}

// ---------------- launch -----------------------------------------------------
extern "C" void kernel_launch(void* const* d_in, const int* in_sizes, int n_in,
                              void* d_out, int out_size) {
    const float* x   = (const float*)d_in[0];
    const int*   ei  = (const int*)d_in[1];     // int32 (JAX default, no x64)
    const float* W1  = (const float*)d_in[2];
    const float* W2  = (const float*)d_in[3];
    const float* W3  = (const float*)d_in[4];
    const float* b   = (const float*)d_in[5];
    const float* gma = (const float*)d_in[6];
    const float* bta = (const float*)d_in[7];
    const float* mu  = (const float*)d_in[8];
    const float* var = (const float*)d_in[9];
    float* out = (float*)d_out;

    init_deg_kernel<<<(NN + 255) / 256, 256>>>();
    count_kernel<<<(EE + 255) / 256, 256>>>(ei + EE);
    partials_kernel<<<NBLK, 256>>>();
    scan_top_kernel<<<1, 128>>>();
    scan_chunks_kernel<<<NBLK, 256>>>();
    bin_kernel<<<(EE + NN + 255) / 256, 256>>>(ei);

    const int GEMM_BLOCKS = (NN + 63) / 64;
    const int SPMM_BLOCKS = (NN * 32 + 255) / 256;

    gemm_kernel<37><<<GEMM_BLOCKS, 256>>>(x, W1, 0);
    spmm_epi_kernel<<<SPMM_BLOCKS, 256>>>(0, b,       gma,       bta,       mu,       var,       out);
    gemm_kernel<64><<<GEMM_BLOCKS, 256>>>(nullptr, W2, 1);
    spmm_epi_kernel<<<SPMM_BLOCKS, 256>>>(1, b + 64,  gma + 64,  bta + 64,  mu + 64,  var + 64,  out);
    gemm_kernel<64><<<GEMM_BLOCKS, 256>>>(nullptr, W3, 2);
    spmm_epi_kernel<<<SPMM_BLOCKS, 256>>>(2, b + 128, gma + 128, bta + 128, mu + 128, var + 128, out);
}